// round 6
// baseline (speedup 1.0000x reference)
#include <cuda_runtime.h>
#include <math.h>

#define N_NODES 20000
#define E_EDGES 640000
#define NHEADS  8
#define ROW     128          // floats per edge in both key and value
#define CAP     128          // edge chunk held in smem (avg degree is 32)

// CSR row offsets for the sorted edge_dst array (device scratch — no allocs).
__device__ int g_off[N_NODES + 1];

__global__ void build_offsets_kernel(const int* __restrict__ dst) {
    int n = blockIdx.x * blockDim.x + threadIdx.x;
    if (n > N_NODES) return;
    // lower_bound(dst, n)
    int lo = 0, hi = E_EDGES;
    while (lo < hi) {
        int mid = (lo + hi) >> 1;
        if (dst[mid] < n) lo = mid + 1; else hi = mid;
    }
    g_off[n] = lo;
}

__global__ __launch_bounds__(128) void attn_se3_kernel(
    const float* __restrict__ key,     // (E, 8, 16)  = E x 128
    const float* __restrict__ q0,      // (N, 32, 1)
    const float* __restrict__ q1,      // (N, 32, 3)
    const float* __restrict__ value,   // (E, 32, 4)  = E x 128
    float* __restrict__ out)           // [N*32] deg-0 part, then [N*32*3] deg-1 part
{
    __shared__ float q_s[ROW];            // fused query for this node, flat (h*16+d)
    __shared__ float ew_s[CAP * NHEADS];  // per-chunk logits, then exp-weights
    __shared__ float m_s[NHEADS];         // running max per head
    __shared__ float s_s[NHEADS];         // running exp-sum per head
    __shared__ float resc_s[NHEADS];      // acc rescale factor per chunk

    const int n    = blockIdx.x;
    const int t    = threadIdx.x;
    const int lane = t & 31;
    const int warp = t >> 5;
    const int h16  = t >> 4;   // head owned by this thread's 16-lane group (softmax role)
    const int i16  = t & 15;
    const int h_t  = t >> 4;   // head for value accumulation (same mapping: c/4 = t/16)

    const int start = g_off[n];
    const int deg   = g_off[n + 1] - start;

    // Load fused query: q_flat[f] with f = c*4+dv; dv==0 -> query_0, else query_1.
    {
        int c = t >> 2, dv = t & 3;
        q_s[t] = (dv == 0) ? q0[n * 32 + c]
                           : q1[(n * 32 + c) * 3 + (dv - 1)];
    }
    if (t < NHEADS) { m_s[t] = -INFINITY; s_s[t] = 0.f; }
    __syncthreads();

    // Per-lane query float4: key flat layout matches q_s flat layout, so lane l
    // covers q_s[4l..4l+3], all inside head l/4.
    const float4 qv = *reinterpret_cast<const float4*>(q_s + lane * 4);

    float acc = 0.f;

    for (int cs = 0; cs < deg; cs += CAP) {
        const int cdeg = min(CAP, deg - cs);

        // ---- 1) logits: one warp per edge, float4 per lane, quad-reduce per head
        #pragma unroll 2
        for (int el = warp; el < cdeg; el += 4) {
            const float4 kv = *reinterpret_cast<const float4*>(
                key + (start + cs + el) * ROW + lane * 4);
            float d = kv.x * qv.x + kv.y * qv.y + kv.z * qv.z + kv.w * qv.w;
            d += __shfl_xor_sync(0xffffffffu, d, 1);
            d += __shfl_xor_sync(0xffffffffu, d, 2);
            if ((lane & 3) == 0)
                ew_s[el * NHEADS + (lane >> 2)] = d * 0.08838834764831843f; // 1/sqrt(128)
        }
        __syncthreads();

        // ---- 2) per-head chunk max (16 lanes per head)
        float m = -INFINITY;
        for (int el = i16; el < cdeg; el += 16)
            m = fmaxf(m, ew_s[el * NHEADS + h16]);
        m = fmaxf(m, __shfl_xor_sync(0xffffffffu, m, 1));
        m = fmaxf(m, __shfl_xor_sync(0xffffffffu, m, 2));
        m = fmaxf(m, __shfl_xor_sync(0xffffffffu, m, 4));
        m = fmaxf(m, __shfl_xor_sync(0xffffffffu, m, 8));

        const float m_old = m_s[h16];
        const float m_new = fmaxf(m_old, m);
        const float sc    = __expf(m_old - m_new);   // 0 on the first chunk

        // ---- 3) exponentiate in place + chunk sum
        float ps = 0.f;
        for (int el = i16; el < cdeg; el += 16) {
            float x = __expf(ew_s[el * NHEADS + h16] - m_new);
            ew_s[el * NHEADS + h16] = x;
            ps += x;
        }
        ps += __shfl_xor_sync(0xffffffffu, ps, 1);
        ps += __shfl_xor_sync(0xffffffffu, ps, 2);
        ps += __shfl_xor_sync(0xffffffffu, ps, 4);
        ps += __shfl_xor_sync(0xffffffffu, ps, 8);
        if (i16 == 0) {
            s_s[h16]    = s_s[h16] * sc + ps;
            m_s[h16]    = m_new;
            resc_s[h16] = sc;
        }
        __syncthreads();

        // ---- 4) value accumulation: thread t owns one of the 128 output floats
        acc *= resc_s[h_t];
        const float* vb = value + (start + cs) * ROW + t;
        int el = 0;
        for (; el + 3 < cdeg; el += 4) {
            const float v0 = vb[(el + 0) * ROW];
            const float v1 = vb[(el + 1) * ROW];
            const float v2 = vb[(el + 2) * ROW];
            const float v3 = vb[(el + 3) * ROW];
            const float w0 = ew_s[(el + 0) * NHEADS + h_t];
            const float w1 = ew_s[(el + 1) * NHEADS + h_t];
            const float w2 = ew_s[(el + 2) * NHEADS + h_t];
            const float w3 = ew_s[(el + 3) * NHEADS + h_t];
            acc += w0 * v0; acc += w1 * v1; acc += w2 * v2; acc += w3 * v3;
        }
        for (; el < cdeg; ++el)
            acc += ew_s[el * NHEADS + h_t] * vb[el * ROW];
        __syncthreads();   // ew_s / resc_s reused next chunk
    }

    // ---- normalize and write split outputs
    if (deg > 0) acc /= s_s[h_t];
    else         acc = 0.f;

    const int c = t >> 2, dv = t & 3;
    if (dv == 0) out[n * 32 + c] = acc;
    else         out[N_NODES * 32 + (n * 32 + c) * 3 + (dv - 1)] = acc;
}

extern "C" void kernel_launch(void* const* d_in, const int* in_sizes, int n_in,
                              void* d_out, int out_size) {
    const float* key   = (const float*)d_in[0];   // (E, 8, 16)
    const float* q0    = (const float*)d_in[1];   // (N, 32, 1)
    const float* q1    = (const float*)d_in[2];   // (N, 32, 3)
    const float* value = (const float*)d_in[3];   // (E, 32, 4)
    const int*   dst   = (const int*)d_in[4];     // (E,) sorted
    float* out = (float*)d_out;

    build_offsets_kernel<<<(N_NODES + 1 + 255) / 256, 256>>>(dst);
    attn_se3_kernel<<<N_NODES, 128>>>(key, q0, q1, value, out);
}

// round 7
// speedup vs baseline: 1.5752x; 1.5752x over previous
#include <cuda_runtime.h>
#include <math.h>

#define N_NODES 20000
#define E_EDGES 640000
#define NHEADS  8
#define ROW     128          // floats per edge in both key and value
#define CAP     128          // edge chunk held in smem (avg degree is 32)

// CSR row offsets for the sorted edge_dst array (device scratch — no allocs).
__device__ int g_off[N_NODES + 1];

// Streaming boundary scatter: off[n] = lower_bound(dst, n). One pass over dst.
__global__ void build_offsets_kernel(const int* __restrict__ dst) {
    int i = blockIdx.x * blockDim.x + threadIdx.x;
    if (i >= E_EDGES) return;
    int d    = dst[i];
    int prev = (i == 0) ? -1 : dst[i - 1];
    for (int n = prev + 1; n <= d; ++n) g_off[n] = i;
    if (i == E_EDGES - 1)
        for (int n = d + 1; n <= N_NODES; ++n) g_off[n] = E_EDGES;
}

__global__ __launch_bounds__(128) void attn_se3_kernel(
    const float* __restrict__ key,     // (E, 8, 16)  = E x 128
    const float* __restrict__ q0,      // (N, 32, 1)
    const float* __restrict__ q1,      // (N, 32, 3)
    const float* __restrict__ value,   // (E, 32, 4)  = E x 128
    float* __restrict__ out)           // [N*32] deg-0 part, then [N*32*3] deg-1 part
{
    __shared__ float  q_s[ROW];                 // fused query, flat (h*16+d)
    __shared__ float  ew_s[2][CAP * NHEADS];    // exp(logit), double-buffered
    __shared__ float  sred_s[4][NHEADS];        // per-warp head sums
    __shared__ float4 vred_s[4][32];            // per-warp value partials (128 cols)

    const int n    = blockIdx.x;
    const int t    = threadIdx.x;
    const int lane = t & 31;
    const int warp = t >> 5;
    const int hq   = lane >> 2;     // head owned by this lane's quad (logit & value roles)

    const int start = g_off[n];
    const int deg   = g_off[n + 1] - start;

    // Load fused query: q_flat[f] with f = c*4+dv; dv==0 -> query_0, else query_1.
    {
        int c = t >> 2, dv = t & 3;
        q_s[t] = (dv == 0) ? q0[n * 32 + c]
                           : q1[(n * 32 + c) * 3 + (dv - 1)];
    }
    __syncthreads();

    // key flat layout matches q_s flat layout: lane l covers q_s[4l..4l+3].
    const float4 qv = *reinterpret_cast<const float4*>(q_s + lane * 4);

    float4 acc  = make_float4(0.f, 0.f, 0.f, 0.f);
    float  hsum = 0.f;              // valid on lanes where (lane&3)==0
    int    buf  = 0;

    for (int cs = 0; cs < deg; cs += CAP) {
        const int cdeg = min(CAP, deg - cs);
        const float* kb = key   + (long)(start + cs) * ROW;
        const float* vb = value + (long)(start + cs) * ROW;

        // ---- 1) logits: warp per edge, float4 per lane, quad-reduce -> exp + head sum
        #pragma unroll 4
        for (int el = warp; el < cdeg; el += 4) {
            const float4 kv = *reinterpret_cast<const float4*>(kb + el * ROW + lane * 4);
            float d = kv.x * qv.x + kv.y * qv.y + kv.z * qv.z + kv.w * qv.w;
            d += __shfl_xor_sync(0xffffffffu, d, 1);
            d += __shfl_xor_sync(0xffffffffu, d, 2);
            if ((lane & 3) == 0) {
                float ex = __expf(d * 0.08838834764831843f);  // 1/sqrt(128)
                ew_s[buf][el * NHEADS + hq] = ex;
                hsum += ex;
            }
        }
        __syncthreads();

        // ---- 2) value accumulation: warp per edge, float4 per lane (cols 4l..4l+3)
        #pragma unroll 4
        for (int el = warp; el < cdeg; el += 4) {
            const float4 v = *reinterpret_cast<const float4*>(vb + el * ROW + lane * 4);
            const float  w = ew_s[buf][el * NHEADS + hq];
            acc.x += w * v.x; acc.y += w * v.y; acc.z += w * v.z; acc.w += w * v.w;
        }
        buf ^= 1;   // no trailing barrier: next chunk's logits write the other buffer
    }

    // ---- cross-warp reduction
    vred_s[warp][lane] = acc;
    if ((lane & 3) == 0) sred_s[warp][hq] = hsum;
    __syncthreads();

    const int   h   = t >> 4;                   // head of output column t
    const float den = sred_s[0][h] + sred_s[1][h] + sred_s[2][h] + sred_s[3][h];
    const float* vr = reinterpret_cast<const float*>(vred_s);
    float v = vr[0 * ROW + t] + vr[1 * ROW + t] + vr[2 * ROW + t] + vr[3 * ROW + t];
    v = (deg > 0) ? v / den : 0.f;

    const int c = t >> 2, dv = t & 3;
    if (dv == 0) out[n * 32 + c] = v;
    else         out[N_NODES * 32 + (n * 32 + c) * 3 + (dv - 1)] = v;
}

extern "C" void kernel_launch(void* const* d_in, const int* in_sizes, int n_in,
                              void* d_out, int out_size) {
    const float* key   = (const float*)d_in[0];   // (E, 8, 16)
    const float* q0    = (const float*)d_in[1];   // (N, 32, 1)
    const float* q1    = (const float*)d_in[2];   // (N, 32, 3)
    const float* value = (const float*)d_in[3];   // (E, 32, 4)
    const int*   dst   = (const int*)d_in[4];     // (E,) sorted
    float* out = (float*)d_out;

    build_offsets_kernel<<<(E_EDGES + 255) / 256, 256>>>(dst);
    attn_se3_kernel<<<N_NODES, 128>>>(key, q0, q1, value, out);
}